// round 15
// baseline (speedup 1.0000x reference)
#include <cuda_runtime.h>

// iPUNet forward, fully fused single kernel. One CTA (128 thr) per point.
// R11 base (13.06us) + transposed smem weights [k][c][3] read as LDS.64 in
// two 3-load tranches (peak 6 live weight regs -- avoids R14's 48-reg blowup
// while keeping most of its instruction saving).
//
// Shapes: B=2, N=1024, FEAT=128, NSAMPLE=48, GRID=7, RADIUS=0.3
// Output (f32, 417792 elems):
//   oris [0,6144) | nors [6144,12288) | pts_ups [12288,110592)
//   pts_offset [110592,116736) | pts_up [116736,417792)

#define NPTS   1024
#define FEATD  128
#define NS     48

#define OFF_ORIS   0
#define OFF_NORS   6144
#define OFF_UPS    12288
#define OFF_OFFSET 110592
#define OFF_PTSUP  116736

__device__ __forceinline__ float wredf(float x) {
#pragma unroll
    for (int o = 16; o; o >>= 1) x += __shfl_xor_sync(0xffffffffu, x, o);
    return x;
}

__global__ __launch_bounds__(128)
void ipunet_kernel(const float* __restrict__ xyz,
                   const float* __restrict__ feat,
                   const float* __restrict__ W0, const float* __restrict__ b0,
                   const float* __restrict__ W1, const float* __restrict__ b1,
                   const float* __restrict__ Wu, const int* __restrict__ g_index,
                   float* __restrict__ out)
{
    const int p    = blockIdx.x;       // global point id 0..2047
    const int b    = p >> 10;
    const int pid  = p & 1023;
    const int t    = threadIdx.x;      // 0..127
    const int lane = t & 31;
    const int warp = t >> 5;           // 0..3

    __shared__ float    s_wu[7 * FEATD * 3];  // TRANSPOSED: [k][c][3], 10.5 KB
    __shared__ float    s_rot[9];
    __shared__ unsigned s_mask[32];
    __shared__ int      s_nbr[NS];
    __shared__ int      s_win[91];
    __shared__ int      s_cnt;
    __shared__ int      s_nwin;
    __shared__ int      s_wlist[NS];    // packed (cell<<10)|nbr
    __shared__ float    s_off[49 * 3];
    __shared__ unsigned s_upmask[49];
    __shared__ float    s_part[4][6];

    // ---- center ----------------------------------------------------------------
    const float* xb = xyz + b * 3 * NPTS;
    const float cx = __ldg(&xb[pid]);
    const float cy = __ldg(&xb[NPTS + pid]);
    const float cz = __ldg(&xb[2 * NPTS + pid]);
    const float thresh = 0.09f - (cx * cx + cy * cy + cz * cz);

    // ---- smem init ----------------------------------------------------------------
    if (t < 91) s_win[t] = -1;
    if (t == 0) s_nwin = 0;
    if (t < 49) s_upmask[t] = 0u;
    s_off[t] = 0.0f;
    if (t < 19) s_off[128 + t] = 0.0f;

    // ---- stage W_unet TRANSPOSED: thread t = channel c -----------------------------
    {
        const int c = t;
        const float* wr = &Wu[c * 21];
#pragma unroll
        for (int k = 0; k < 7; k++) {
            s_wu[k * 384 + c * 3 + 0] = __ldg(&wr[k * 3 + 0]);
            s_wu[k * 384 + c * 3 + 1] = __ldg(&wr[k * 3 + 1]);
            s_wu[k * 384 + c * 3 + 2] = __ldg(&wr[k * 3 + 2]);
        }
    }

    // ---- merged: ball query (8 segs) + oris/nors matvec -----------------------------
    {
        float f   = __ldg(&feat[(p << 7) + t]);
        float w0a = __ldg(&W0[t]), w0b = __ldg(&W0[128 + t]), w0c = __ldg(&W0[256 + t]);
        float w1a = __ldg(&W1[t]), w1b = __ldg(&W1[128 + t]), w1c = __ldg(&W1[256 + t]);

#pragma unroll
        for (int seg = 0; seg < 8; seg++) {
            int j = seg * 128 + t;
            float px = __ldg(&xb[j]);
            float py = __ldg(&xb[NPTS + j]);
            float pz = __ldg(&xb[2 * NPTS + j]);
            float d = (px * px + py * py + pz * pz)
                      - 2.0f * (cx * px + cy * py + cz * pz);
            unsigned m = __ballot_sync(0xffffffffu, !(d > thresh));
            if (lane == 0) s_mask[seg * 4 + warp] = m;
        }

        float q0 = wredf(f * w0a), q1 = wredf(f * w0b), q2 = wredf(f * w0c);
        float q3 = wredf(f * w1a), q4 = wredf(f * w1b), q5 = wredf(f * w1c);
        if (lane == 0) {
            s_part[warp][0] = q0; s_part[warp][1] = q1; s_part[warp][2] = q2;
            s_part[warp][3] = q3; s_part[warp][4] = q4; s_part[warp][5] = q5;
        }
    }
    __syncthreads();

    // ---- concurrent: rotation (t==32) | extraction (warp 0) | upmask (warp 2) -------
    if (t >= 64 && t < 80)
        atomicOr(&s_upmask[__ldg(&g_index[t - 64])], 1u << (t - 64));

    if (t == 32) {
        float ov[3], nv[3];
#pragma unroll
        for (int d = 0; d < 3; d++) {
            ov[d] = s_part[0][d]   + s_part[1][d]   + s_part[2][d]   + s_part[3][d]   + __ldg(&b0[d]);
            nv[d] = s_part[0][3+d] + s_part[1][3+d] + s_part[2][3+d] + s_part[3][3+d] + __ldg(&b1[d]);
        }
        float io = 1.0f / (sqrtf(ov[0]*ov[0]+ov[1]*ov[1]+ov[2]*ov[2] + 1e-8f) + 1e-10f);
        ov[0] *= io; ov[1] *= io; ov[2] *= io;
        float in = 1.0f / (sqrtf(nv[0]*nv[0]+nv[1]*nv[1]+nv[2]*nv[2] + 1e-8f) + 1e-10f);
        nv[0] *= in; nv[1] *= in; nv[2] *= in;

        float r90[3];
        r90[0] = ov[1]*nv[2] - ov[2]*nv[1];
        r90[1] = ov[2]*nv[0] - ov[0]*nv[2];
        r90[2] = ov[0]*nv[1] - ov[1]*nv[0];
        float ir = 1.0f / (sqrtf(r90[0]*r90[0]+r90[1]*r90[1]+r90[2]*r90[2] + 1e-8f) + 1e-10f);
        r90[0] *= ir; r90[1] *= ir; r90[2] *= ir;

        float o0[3];
        o0[0] = r90[1]*nv[2] - r90[2]*nv[1];
        o0[1] = r90[2]*nv[0] - r90[0]*nv[2];
        o0[2] = r90[0]*nv[1] - r90[1]*nv[0];
        float i0 = 1.0f / (sqrtf(o0[0]*o0[0]+o0[1]*o0[1]+o0[2]*o0[2] + 1e-8f) + 1e-10f);
        o0[0] *= i0; o0[1] *= i0; o0[2] *= i0;

        s_rot[0] = o0[0];  s_rot[1] = o0[1];  s_rot[2] = o0[2];
        s_rot[3] = r90[0]; s_rot[4] = r90[1]; s_rot[5] = r90[2];
        s_rot[6] = nv[0];  s_rot[7] = nv[1];  s_rot[8] = nv[2];

#pragma unroll
        for (int d = 0; d < 3; d++) {
            out[OFF_ORIS + p * 3 + d] = ov[d];
            out[OFF_NORS + p * 3 + d] = nv[d];
        }
    }
    if (warp == 0) {
        unsigned m = s_mask[lane];
        int pc = __popc(m);
        int incl = pc;
#pragma unroll
        for (int o = 1; o < 32; o <<= 1) {
            int v = __shfl_up_sync(0xffffffffu, incl, o);
            if (lane >= o) incl += v;
        }
        int excl = incl - pc;
        if (lane == 31) s_cnt = (incl < NS) ? incl : NS;
        unsigned mm = m;
        int r = excl;
        while (mm && r < NS) {
            int bpos = __ffs(mm) - 1;
            s_nbr[r] = (lane << 5) + bpos;
            mm &= mm - 1;
            r++;
        }
    }
    __syncthreads();

    // ---- local coords -> cell; last-wins winner; compact ------------------------------
    int myCell = -1, myJ = 0;
    if (t < NS) {
        myJ = (t < s_cnt) ? s_nbr[t] : s_nbr[0];
        float lx = __ldg(&xb[myJ]) - cx;
        float ly = __ldg(&xb[NPTS + myJ]) - cy;
        float lz = __ldg(&xb[2 * NPTS + myJ]) - cz;
        int c[3];
#pragma unroll
        for (int d = 0; d < 3; d++) {
            float lp = lx * s_rot[d*3+0] + ly * s_rot[d*3+1] + lz * s_rot[d*3+2];
            float v = rintf((lp + 0.3f) / 0.6f * 6.0f);
            int ci = (int)v;
            ci = ci < 0 ? 0 : (ci > 6 ? 6 : ci);
            c[d] = ci;
        }
        myCell = c[0] * 7 + c[1] * 7 + c[2];   // reference quirk: both *g
        atomicMax(&s_win[myCell], t);
    }
    __syncthreads();
    if (t < NS && s_win[myCell] == t) {
        int w = atomicAdd(&s_nwin, 1);
        s_wlist[w] = (myCell << 10) | myJ;
    }
    __syncthreads();

    // ---- sparse feat_off: 4 winners/warp-iter, 8 lanes/winner, LDS.64 weights ---------
    {
        const int nw = s_nwin;
        const float4* fb = (const float4*)(feat + ((long)b << 17));
        const int sub  = lane >> 3;
        const int lsub = lane & 7;

        for (int g = warp * 4; g < nw; g += 16) {
            int i = g + sub;
            bool valid = (i < nw);
            int pk   = s_wlist[valid ? i : 0];
            int cell = pk >> 10;
            int nbr  = pk & 1023;

            // channels c = lsub*4 + blk*32 + {0..3}
            float4 v0 = __ldg(&fb[(nbr << 5) + lsub]);
            float4 v1 = __ldg(&fb[(nbr << 5) + lsub + 8]);
            float4 v2 = __ldg(&fb[(nbr << 5) + lsub + 16]);
            float4 v3 = __ldg(&fb[(nbr << 5) + lsub + 24]);

            int k  = cell % 7;
            int p5 = (cell / 49) * 7 + (cell / 7) % 7;

            float a0 = 0.f, a1 = 0.f, a2 = 0.f;
            // transposed weights: [k][c][3]; per blk 12 consecutive floats,
            // read as 6 LDS.64 in two tranches of 3 (low register pressure)
            const float2* wk = (const float2*)&s_wu[k * 384 + lsub * 12];
#pragma unroll
            for (int blk = 0; blk < 4; blk++) {
                float4 v = (blk == 0) ? v0 : (blk == 1) ? v1 : (blk == 2) ? v2 : v3;
                const float2* wb2 = wk + blk * 48;   // blk*96 floats = blk*48 float2
                {   // tranche 1: channels c0, c0+1
                    float2 wa = wb2[0], wbv = wb2[1], wc = wb2[2];
                    a0 += v.x * wa.x  + v.y * wbv.y;
                    a1 += v.x * wa.y  + v.y * wc.x;
                    a2 += v.x * wbv.x + v.y * wc.y;
                }
                {   // tranche 2: channels c0+2, c0+3
                    float2 wd = wb2[3], we = wb2[4], wf = wb2[5];
                    a0 += v.z * wd.x + v.w * we.y;
                    a1 += v.z * wd.y + v.w * wf.x;
                    a2 += v.z * we.x + v.w * wf.y;
                }
            }

            // reduce within each 8-lane group
            a0 += __shfl_xor_sync(0xffffffffu, a0, 4);
            a1 += __shfl_xor_sync(0xffffffffu, a1, 4);
            a2 += __shfl_xor_sync(0xffffffffu, a2, 4);
            a0 += __shfl_xor_sync(0xffffffffu, a0, 2);
            a1 += __shfl_xor_sync(0xffffffffu, a1, 2);
            a2 += __shfl_xor_sync(0xffffffffu, a2, 2);
            a0 += __shfl_xor_sync(0xffffffffu, a0, 1);
            a1 += __shfl_xor_sync(0xffffffffu, a1, 1);
            a2 += __shfl_xor_sync(0xffffffffu, a2, 1);

            if (lsub == 0 && valid) {
                atomicAdd(&s_off[p5 * 3 + 0], a0);
                atomicAdd(&s_off[p5 * 3 + 1], a1);
                atomicAdd(&s_off[p5 * 3 + 2], a2);
            }
        }
    }
    __syncthreads();

    // ---- up = vals + feat_off; rotate back; write outputs -------------------------------
    if (t < 49) {
        int s = t;
        float u0 = (float)(s / 7 - 3) * 0.1f + s_off[s * 3 + 0];
        float u1 = (float)(s % 7 - 3) * 0.1f + s_off[s * 3 + 1];
        float u2 = s_off[s * 3 + 2];
        float w[3];
#pragma unroll
        for (int d = 0; d < 3; d++)
            w[d] = u0 * s_rot[d] + u1 * s_rot[3 + d] + u2 * s_rot[6 + d]
                 + (d == 0 ? cx : (d == 1 ? cy : cz));

        float* o_up = out + OFF_PTSUP + (p * 49 + s) * 3;
        o_up[0] = w[0]; o_up[1] = w[1]; o_up[2] = w[2];

        if (s == 24) {
            float* o_of = out + OFF_OFFSET + p * 3;
            o_of[0] = w[0]; o_of[1] = w[1]; o_of[2] = w[2];
        }
        unsigned m = s_upmask[s];
        while (m) {
            int q = __ffs(m) - 1;
            m &= m - 1;
            float* o_u = out + OFF_UPS + (p * 16 + q) * 3;
            o_u[0] = w[0]; o_u[1] = w[1]; o_u[2] = w[2];
        }
    }
}

extern "C" void kernel_launch(void* const* d_in, const int* in_sizes, int n_in,
                              void* d_out, int out_size)
{
    const float* xyz   = (const float*)d_in[0];
    const float* feat  = (const float*)d_in[1];
    const float* W0    = (const float*)d_in[2];
    const float* b0    = (const float*)d_in[3];
    const float* W1    = (const float*)d_in[4];
    const float* b1    = (const float*)d_in[5];
    const float* Wu    = (const float*)d_in[6];
    const int*   index = (const int*)d_in[7];
    float* out = (float*)d_out;

    ipunet_kernel<<<2048, 128>>>(xyz, feat, W0, b0, W1, b1, Wu, index, out);
}

// round 16
// speedup vs baseline: 1.3200x; 1.3200x over previous
#include <cuda_runtime.h>

// iPUNet forward, fully fused single kernel. One CTA (128 thr) per point.
// R11 (13.06us, best) + safe instruction trims:
//   - c2 folded into ball-query threshold
//   - cell -> (k, p5) decoded once at compact time, packed into s_wlist
//   - minor hoists
// Layout and register envelope identical to R11 (regs=32, smem ~13KB).
//
// Shapes: B=2, N=1024, FEAT=128, NSAMPLE=48, GRID=7, RADIUS=0.3
// Output (f32, 417792 elems):
//   oris [0,6144) | nors [6144,12288) | pts_ups [12288,110592)
//   pts_offset [110592,116736) | pts_up [116736,417792)

#define NPTS   1024
#define FEATD  128
#define NS     48

#define OFF_ORIS   0
#define OFF_NORS   6144
#define OFF_UPS    12288
#define OFF_OFFSET 110592
#define OFF_PTSUP  116736

__device__ __forceinline__ float wredf(float x) {
#pragma unroll
    for (int o = 16; o; o >>= 1) x += __shfl_xor_sync(0xffffffffu, x, o);
    return x;
}

__global__ __launch_bounds__(128)
void ipunet_kernel(const float* __restrict__ xyz,
                   const float* __restrict__ feat,
                   const float* __restrict__ W0, const float* __restrict__ b0,
                   const float* __restrict__ W1, const float* __restrict__ b1,
                   const float* __restrict__ Wu, const int* __restrict__ g_index,
                   float* __restrict__ out)
{
    const int p    = blockIdx.x;       // global point id 0..2047
    const int b    = p >> 10;
    const int pid  = p & 1023;
    const int t    = threadIdx.x;      // 0..127
    const int lane = t & 31;
    const int warp = t >> 5;           // 0..3

    __shared__ float    s_wu[FEATD * 21];   // W_unet [c][21] (10.5 KB) -- R11 layout
    __shared__ float    s_rot[9];
    __shared__ unsigned s_mask[32];
    __shared__ int      s_nbr[NS];
    __shared__ int      s_win[91];
    __shared__ int      s_cnt;
    __shared__ int      s_nwin;
    __shared__ int      s_wlist[NS];    // packed (p5<<13)|(k<<10)|nbr
    __shared__ float    s_off[49 * 3];
    __shared__ unsigned s_upmask[49];
    __shared__ float    s_part[4][6];

    // ---- center ----------------------------------------------------------------
    const float* xb = xyz + b * 3 * NPTS;
    const float cx = __ldg(&xb[pid]);
    const float cy = __ldg(&xb[NPTS + pid]);
    const float cz = __ldg(&xb[2 * NPTS + pid]);
    const float thresh = 0.09f - (cx * cx + cy * cy + cz * cz);

    // ---- smem init ----------------------------------------------------------------
    if (t < 91) s_win[t] = -1;
    if (t == 0) s_nwin = 0;
    if (t < 49) s_upmask[t] = 0u;
    s_off[t] = 0.0f;
    if (t < 19) s_off[128 + t] = 0.0f;

    // ---- stage W_unet into smem (672 float4s across 128 threads) -------------------
    {
        const float4* wu4 = (const float4*)Wu;
        float4* sw4 = (float4*)s_wu;
#pragma unroll
        for (int i = 0; i < 5; i++)
            sw4[t + i * 128] = __ldg(&wu4[t + i * 128]);
        if (t < 32) sw4[t + 640] = __ldg(&wu4[t + 640]);
    }

    // ---- merged: ball query (8 segs) + oris/nors matvec -----------------------------
    {
        float f   = __ldg(&feat[(p << 7) + t]);
        float w0a = __ldg(&W0[t]), w0b = __ldg(&W0[128 + t]), w0c = __ldg(&W0[256 + t]);
        float w1a = __ldg(&W1[t]), w1b = __ldg(&W1[128 + t]), w1c = __ldg(&W1[256 + t]);

        const float* xp = xb + t;
        const float* yp = xb + NPTS + t;
        const float* zp = xb + 2 * NPTS + t;
#pragma unroll
        for (int seg = 0; seg < 8; seg++) {
            float px = __ldg(xp + seg * 128);
            float py = __ldg(yp + seg * 128);
            float pz = __ldg(zp + seg * 128);
            float d = (px * px + py * py + pz * pz)
                      - 2.0f * (cx * px + cy * py + cz * pz);
            unsigned m = __ballot_sync(0xffffffffu, !(d > thresh));
            if (lane == 0) s_mask[seg * 4 + warp] = m;
        }

        float q0 = wredf(f * w0a), q1 = wredf(f * w0b), q2 = wredf(f * w0c);
        float q3 = wredf(f * w1a), q4 = wredf(f * w1b), q5 = wredf(f * w1c);
        if (lane == 0) {
            s_part[warp][0] = q0; s_part[warp][1] = q1; s_part[warp][2] = q2;
            s_part[warp][3] = q3; s_part[warp][4] = q4; s_part[warp][5] = q5;
        }
    }
    __syncthreads();

    // ---- concurrent: rotation (t==32) | extraction (warp 0) | upmask (warp 2) -------
    if (t >= 64 && t < 80)
        atomicOr(&s_upmask[__ldg(&g_index[t - 64])], 1u << (t - 64));

    if (t == 32) {
        float ov[3], nv[3];
#pragma unroll
        for (int d = 0; d < 3; d++) {
            ov[d] = s_part[0][d]   + s_part[1][d]   + s_part[2][d]   + s_part[3][d]   + __ldg(&b0[d]);
            nv[d] = s_part[0][3+d] + s_part[1][3+d] + s_part[2][3+d] + s_part[3][3+d] + __ldg(&b1[d]);
        }
        float io = 1.0f / (sqrtf(ov[0]*ov[0]+ov[1]*ov[1]+ov[2]*ov[2] + 1e-8f) + 1e-10f);
        ov[0] *= io; ov[1] *= io; ov[2] *= io;
        float in = 1.0f / (sqrtf(nv[0]*nv[0]+nv[1]*nv[1]+nv[2]*nv[2] + 1e-8f) + 1e-10f);
        nv[0] *= in; nv[1] *= in; nv[2] *= in;

        float r90[3];
        r90[0] = ov[1]*nv[2] - ov[2]*nv[1];
        r90[1] = ov[2]*nv[0] - ov[0]*nv[2];
        r90[2] = ov[0]*nv[1] - ov[1]*nv[0];
        float ir = 1.0f / (sqrtf(r90[0]*r90[0]+r90[1]*r90[1]+r90[2]*r90[2] + 1e-8f) + 1e-10f);
        r90[0] *= ir; r90[1] *= ir; r90[2] *= ir;

        float o0[3];
        o0[0] = r90[1]*nv[2] - r90[2]*nv[1];
        o0[1] = r90[2]*nv[0] - r90[0]*nv[2];
        o0[2] = r90[0]*nv[1] - r90[1]*nv[0];
        float i0 = 1.0f / (sqrtf(o0[0]*o0[0]+o0[1]*o0[1]+o0[2]*o0[2] + 1e-8f) + 1e-10f);
        o0[0] *= i0; o0[1] *= i0; o0[2] *= i0;

        s_rot[0] = o0[0];  s_rot[1] = o0[1];  s_rot[2] = o0[2];
        s_rot[3] = r90[0]; s_rot[4] = r90[1]; s_rot[5] = r90[2];
        s_rot[6] = nv[0];  s_rot[7] = nv[1];  s_rot[8] = nv[2];

#pragma unroll
        for (int d = 0; d < 3; d++) {
            out[OFF_ORIS + p * 3 + d] = ov[d];
            out[OFF_NORS + p * 3 + d] = nv[d];
        }
    }
    if (warp == 0) {
        unsigned m = s_mask[lane];
        int pc = __popc(m);
        int incl = pc;
#pragma unroll
        for (int o = 1; o < 32; o <<= 1) {
            int v = __shfl_up_sync(0xffffffffu, incl, o);
            if (lane >= o) incl += v;
        }
        int excl = incl - pc;
        if (lane == 31) s_cnt = (incl < NS) ? incl : NS;
        unsigned mm = m;
        int r = excl;
        while (mm && r < NS) {
            int bpos = __ffs(mm) - 1;
            s_nbr[r] = (lane << 5) + bpos;
            mm &= mm - 1;
            r++;
        }
    }
    __syncthreads();

    // ---- local coords -> cell; last-wins winner; compact ------------------------------
    int myCell = -1, myJ = 0;
    if (t < NS) {
        myJ = (t < s_cnt) ? s_nbr[t] : s_nbr[0];
        float lx = __ldg(&xb[myJ]) - cx;
        float ly = __ldg(&xb[NPTS + myJ]) - cy;
        float lz = __ldg(&xb[2 * NPTS + myJ]) - cz;
        int c[3];
#pragma unroll
        for (int d = 0; d < 3; d++) {
            float lp = lx * s_rot[d*3+0] + ly * s_rot[d*3+1] + lz * s_rot[d*3+2];
            float v = rintf((lp + 0.3f) / 0.6f * 6.0f);
            int ci = (int)v;
            ci = ci < 0 ? 0 : (ci > 6 ? 6 : ci);
            c[d] = ci;
        }
        myCell = c[0] * 7 + c[1] * 7 + c[2];   // reference quirk: both *g
        atomicMax(&s_win[myCell], t);
    }
    __syncthreads();
    if (t < NS && s_win[myCell] == t) {
        int w = atomicAdd(&s_nwin, 1);
        int k  = myCell % 7;
        int p5 = (myCell / 49) * 7 + (myCell / 7) % 7;
        s_wlist[w] = (p5 << 13) | (k << 10) | myJ;   // pre-decoded
    }
    __syncthreads();

    // ---- sparse feat_off: 4 winners/warp-iter, 8 lanes/winner, SMEM weights -----------
    {
        const int nw = s_nwin;
        const float4* fb = (const float4*)(feat + ((long)b << 17));
        const int sub  = lane >> 3;
        const int lsub = lane & 7;

        for (int g = warp * 4; g < nw; g += 16) {
            int i = g + sub;
            bool valid = (i < nw);
            int pk  = s_wlist[valid ? i : 0];
            int nbr = pk & 1023;
            int k   = (pk >> 10) & 7;
            int p5  = pk >> 13;

            // channels: c = lsub*4 + blk*32 + {0..3}
            float4 v0 = __ldg(&fb[(nbr << 5) + lsub]);
            float4 v1 = __ldg(&fb[(nbr << 5) + lsub + 8]);
            float4 v2 = __ldg(&fb[(nbr << 5) + lsub + 16]);
            float4 v3 = __ldg(&fb[(nbr << 5) + lsub + 24]);

            const float* wb = &s_wu[(lsub << 2) * 21 + k * 3];
            float a0, a1, a2;
            {
                const float* w0p = wb;               // blk 0
                a0  = v0.x*w0p[0]  + v0.y*w0p[21] + v0.z*w0p[42] + v0.w*w0p[63];
                a1  = v0.x*w0p[1]  + v0.y*w0p[22] + v0.z*w0p[43] + v0.w*w0p[64];
                a2  = v0.x*w0p[2]  + v0.y*w0p[23] + v0.z*w0p[44] + v0.w*w0p[65];
                const float* w1p = wb + 32 * 21;     // blk 1
                a0 += v1.x*w1p[0]  + v1.y*w1p[21] + v1.z*w1p[42] + v1.w*w1p[63];
                a1 += v1.x*w1p[1]  + v1.y*w1p[22] + v1.z*w1p[43] + v1.w*w1p[64];
                a2 += v1.x*w1p[2]  + v1.y*w1p[23] + v1.z*w1p[44] + v1.w*w1p[65];
                const float* w2p = wb + 64 * 21;     // blk 2
                a0 += v2.x*w2p[0]  + v2.y*w2p[21] + v2.z*w2p[42] + v2.w*w2p[63];
                a1 += v2.x*w2p[1]  + v2.y*w2p[22] + v2.z*w2p[43] + v2.w*w2p[64];
                a2 += v2.x*w2p[2]  + v2.y*w2p[23] + v2.z*w2p[44] + v2.w*w2p[65];
                const float* w3p = wb + 96 * 21;     // blk 3
                a0 += v3.x*w3p[0]  + v3.y*w3p[21] + v3.z*w3p[42] + v3.w*w3p[63];
                a1 += v3.x*w3p[1]  + v3.y*w3p[22] + v3.z*w3p[43] + v3.w*w3p[64];
                a2 += v3.x*w3p[2]  + v3.y*w3p[23] + v3.z*w3p[44] + v3.w*w3p[65];
            }

            // reduce within each 8-lane group
            a0 += __shfl_xor_sync(0xffffffffu, a0, 4);
            a1 += __shfl_xor_sync(0xffffffffu, a1, 4);
            a2 += __shfl_xor_sync(0xffffffffu, a2, 4);
            a0 += __shfl_xor_sync(0xffffffffu, a0, 2);
            a1 += __shfl_xor_sync(0xffffffffu, a1, 2);
            a2 += __shfl_xor_sync(0xffffffffu, a2, 2);
            a0 += __shfl_xor_sync(0xffffffffu, a0, 1);
            a1 += __shfl_xor_sync(0xffffffffu, a1, 1);
            a2 += __shfl_xor_sync(0xffffffffu, a2, 1);

            if (lsub == 0 && valid) {
                atomicAdd(&s_off[p5 * 3 + 0], a0);
                atomicAdd(&s_off[p5 * 3 + 1], a1);
                atomicAdd(&s_off[p5 * 3 + 2], a2);
            }
        }
    }
    __syncthreads();

    // ---- up = vals + feat_off; rotate back; write outputs -------------------------------
    if (t < 49) {
        int s = t;
        float u0 = (float)(s / 7 - 3) * 0.1f + s_off[s * 3 + 0];
        float u1 = (float)(s % 7 - 3) * 0.1f + s_off[s * 3 + 1];
        float u2 = s_off[s * 3 + 2];
        float w[3];
#pragma unroll
        for (int d = 0; d < 3; d++)
            w[d] = u0 * s_rot[d] + u1 * s_rot[3 + d] + u2 * s_rot[6 + d]
                 + (d == 0 ? cx : (d == 1 ? cy : cz));

        float* o_up = out + OFF_PTSUP + (p * 49 + s) * 3;
        o_up[0] = w[0]; o_up[1] = w[1]; o_up[2] = w[2];

        if (s == 24) {
            float* o_of = out + OFF_OFFSET + p * 3;
            o_of[0] = w[0]; o_of[1] = w[1]; o_of[2] = w[2];
        }
        unsigned m = s_upmask[s];
        while (m) {
            int q = __ffs(m) - 1;
            m &= m - 1;
            float* o_u = out + OFF_UPS + (p * 16 + q) * 3;
            o_u[0] = w[0]; o_u[1] = w[1]; o_u[2] = w[2];
        }
    }
}

extern "C" void kernel_launch(void* const* d_in, const int* in_sizes, int n_in,
                              void* d_out, int out_size)
{
    const float* xyz   = (const float*)d_in[0];
    const float* feat  = (const float*)d_in[1];
    const float* W0    = (const float*)d_in[2];
    const float* b0    = (const float*)d_in[3];
    const float* W1    = (const float*)d_in[4];
    const float* b1    = (const float*)d_in[5];
    const float* Wu    = (const float*)d_in[6];
    const int*   index = (const int*)d_in[7];
    float* out = (float*)d_out;

    ipunet_kernel<<<2048, 128>>>(xyz, feat, W0, b0, W1, b1, Wu, index, out);
}